// round 2
// baseline (speedup 1.0000x reference)
#include <cuda_runtime.h>
#include <math.h>

// Problem constants
#define BATCH 32
#define SEQ   1024
#define HID   512
#define NH    8
#define DH    64                 // head dim = 512/8
#define ROWS  (BATCH*SEQ)        // 32768
#define NEGV  (-4294967295.0f)   // -(2^32)+1, matches reference mask value

// ---------------- scratch (static device globals; no allocations) ----------
__device__ float g_q[(size_t)ROWS * HID];
__device__ float g_k[(size_t)ROWS * HID];
__device__ float g_v[(size_t)ROWS * HID];
__device__ float g_qmask[ROWS];
__device__ float g_kmask[ROWS];

// ---------------- kernel 1: masks -----------------------------------------
// qmask[b,s] = sign(|sum_h queries|), kmask likewise for keys.
// One warp per row; 2*ROWS rows total.
__global__ void mask_kernel(const float* __restrict__ queries,
                            const float* __restrict__ keys) {
    int row  = blockIdx.x * 8 + (threadIdx.x >> 5);   // 0 .. 2*ROWS-1
    int lane = threadIdx.x & 31;
    const float* src;
    float* dst;
    if (row < ROWS) { src = queries + (size_t)row * HID; dst = g_qmask + row; }
    else            { src = keys + (size_t)(row - ROWS) * HID; dst = g_kmask + (row - ROWS); }
    float s = 0.f;
#pragma unroll
    for (int i = 0; i < HID / 32; i++) s += src[lane + i * 32];
#pragma unroll
    for (int off = 16; off > 0; off >>= 1) s += __shfl_xor_sync(0xFFFFFFFFu, s, off);
    if (lane == 0) *dst = (s != 0.0f) ? 1.0f : 0.0f;
}

// ---------------- kernel 2: QKV projection GEMM ----------------------------
// C[M=32768, N=512] = A @ W + bias.  128x128 tile, TK=8, 256 threads, 8x8/thread.
// blockIdx.z selects (A, W, bias, C) among the three projections.
__global__ __launch_bounds__(256, 2)
void gemm_qkv(const float* __restrict__ queries, const float* __restrict__ keys,
              const float* __restrict__ Wq, const float* __restrict__ bq,
              const float* __restrict__ Wk, const float* __restrict__ bk,
              const float* __restrict__ Wv, const float* __restrict__ bv) {
    const float* A; const float* W; const float* bias; float* C;
    if (blockIdx.z == 0)      { A = queries; W = Wq; bias = bq; C = g_q; }
    else if (blockIdx.z == 1) { A = keys;    W = Wk; bias = bk; C = g_k; }
    else                      { A = keys;    W = Wv; bias = bv; C = g_v; }

    __shared__ float As[8][128];   // A tile, transposed: As[k][m]
    __shared__ float Bs[8][128];   // W tile: Bs[k][n]

    const int tid = threadIdx.x;
    const int m0  = blockIdx.y * 128;
    const int n0  = blockIdx.x * 128;
    const int rb  = (tid >> 4) * 8;       // 16 row groups
    const int cb  = (tid & 15) * 8;       // 16 col groups

    // load indices
    const int la_r  = tid >> 1;           // 0..127
    const int la_k  = (tid & 1) * 4;      // 0 or 4
    const int lb_k  = tid >> 5;           // 0..7
    const int lb_c  = (tid & 31) * 4;     // 0..124

    float acc[8][8];
#pragma unroll
    for (int i = 0; i < 8; i++)
#pragma unroll
        for (int j = 0; j < 8; j++) acc[i][j] = 0.f;

    for (int k0 = 0; k0 < HID; k0 += 8) {
        float4 av = *(const float4*)&A[(size_t)(m0 + la_r) * HID + k0 + la_k];
        As[la_k + 0][la_r] = av.x;
        As[la_k + 1][la_r] = av.y;
        As[la_k + 2][la_r] = av.z;
        As[la_k + 3][la_r] = av.w;
        *(float4*)&Bs[lb_k][lb_c] = *(const float4*)&W[(size_t)(k0 + lb_k) * HID + n0 + lb_c];
        __syncthreads();
#pragma unroll
        for (int kk = 0; kk < 8; kk++) {
            float a[8], b[8];
            *(float4*)&a[0] = *(float4*)&As[kk][rb];
            *(float4*)&a[4] = *(float4*)&As[kk][rb + 4];
            *(float4*)&b[0] = *(float4*)&Bs[kk][cb];
            *(float4*)&b[4] = *(float4*)&Bs[kk][cb + 4];
#pragma unroll
            for (int i = 0; i < 8; i++)
#pragma unroll
                for (int j = 0; j < 8; j++) acc[i][j] += a[i] * b[j];
        }
        __syncthreads();
    }

#pragma unroll
    for (int i = 0; i < 8; i++) {
        size_t mrow = (size_t)(m0 + rb + i) * HID;
#pragma unroll
        for (int j = 0; j < 8; j += 4) {
            float4 o;
            o.x = acc[i][j + 0] + bias[n0 + cb + j + 0];
            o.y = acc[i][j + 1] + bias[n0 + cb + j + 1];
            o.z = acc[i][j + 2] + bias[n0 + cb + j + 2];
            o.w = acc[i][j + 3] + bias[n0 + cb + j + 3];
            *(float4*)&C[mrow + n0 + cb + j] = o;
        }
    }
}

// ---------------- kernel 3: flash attention --------------------------------
// grid (16 q-tiles, 32 batch, 8 heads), 256 threads.
// Q tile 64 rows x d=64; K/V tiles 32 keys x 64; static shared only (~44 KB,
// under the 48 KB static limit -> no cudaFuncSetAttribute in the capture path).
// Online softmax; causal tile skipping; epilogue applies 1/l, query mask,
// and the residual (+queries).
#define TPAD 68   // row stride for 64-wide Q/K/V tiles (float4-aligned, conflict-skewed)
#define PPAD 36   // row stride for the 32-wide P tile

__global__ __launch_bounds__(256)
void attn_kernel(const float* __restrict__ queries, float* __restrict__ out) {
    const int qt = blockIdx.x;   // 0..15  (64-row query tile)
    const int b  = blockIdx.y;   // 0..31
    const int h  = blockIdx.z;   // 0..7

    __shared__ float Qs[64 * TPAD];      // 17408 B
    __shared__ float Ks[32 * TPAD];      //  8704 B
    __shared__ float Vs[32 * TPAD];      //  8704 B
    __shared__ float Ps[64 * PPAD];      //  9216 B
    __shared__ float m_run[64], l_run[64], scl[64], kmsk[32];

    const int tid  = threadIdx.x;
    const int r0   = (tid >> 4) * 4;     // 4 query rows per thread
    const int c0s  = (tid & 15) * 2;     // 2 key cols per thread (S compute)
    const int c0   = (tid & 15) * 4;     // 4 out cols per thread (PV)
    const int wid  = tid >> 5;
    const int lane = tid & 31;

    const size_t headoff = (size_t)b * SEQ * HID + h * DH;
    const float* qbase = g_q + headoff;
    const float* kbase = g_k + headoff;
    const float* vbase = g_v + headoff;

    // load Q tile (64 rows x 64 dims)
#pragma unroll
    for (int i = 0; i < 4; i++) {
        int idx = tid + i * 256;         // 0..1023
        int row = idx >> 4;
        int d4  = (idx & 15) * 4;
        *(float4*)&Qs[row * TPAD + d4] =
            *(const float4*)&qbase[(size_t)(qt * 64 + row) * HID + d4];
    }
    if (tid < 64) { m_run[tid] = -3.0e38f; l_run[tid] = 0.f; }

    float o[4][4];
#pragma unroll
    for (int i = 0; i < 4; i++)
#pragma unroll
        for (int j = 0; j < 4; j++) o[i][j] = 0.f;

    const float scale = 0.04419417382415922f;  // 1/sqrt(512)
    const int n_kt = 2 * qt + 2;               // 32-key tiles covering causal span

    for (int kt = 0; kt < n_kt; kt++) {
        __syncthreads();
        // load K, V tiles (32 rows x 64 dims) + key mask
#pragma unroll
        for (int i = 0; i < 2; i++) {
            int idx = tid + i * 256;     // 0..511
            int row = idx >> 4;
            int d4  = (idx & 15) * 4;
            size_t g = (size_t)(kt * 32 + row) * HID + d4;
            *(float4*)&Ks[row * TPAD + d4] = *(const float4*)&kbase[g];
            *(float4*)&Vs[row * TPAD + d4] = *(const float4*)&vbase[g];
        }
        if (tid < 32) kmsk[tid] = g_kmask[b * SEQ + kt * 32 + tid];
        __syncthreads();

        // S = Q K^T  (4 rows x 2 cols per thread)
        float s[4][2];
#pragma unroll
        for (int i = 0; i < 4; i++) { s[i][0] = 0.f; s[i][1] = 0.f; }
#pragma unroll
        for (int d0 = 0; d0 < DH; d0 += 4) {
            float4 qv[4], kv[2];
#pragma unroll
            for (int i = 0; i < 4; i++) qv[i] = *(float4*)&Qs[(r0 + i) * TPAD + d0];
#pragma unroll
            for (int j = 0; j < 2; j++) kv[j] = *(float4*)&Ks[(c0s + j) * TPAD + d0];
#pragma unroll
            for (int i = 0; i < 4; i++)
#pragma unroll
                for (int j = 0; j < 2; j++) {
                    s[i][j] += qv[i].x * kv[j].x + qv[i].y * kv[j].y
                             + qv[i].z * kv[j].z + qv[i].w * kv[j].w;
                }
        }
        // scale + masks, stage into Ps
#pragma unroll
        for (int i = 0; i < 4; i++) {
            int qg = qt * 64 + r0 + i;
#pragma unroll
            for (int j = 0; j < 2; j++) {
                int kg = kt * 32 + c0s + j;
                float v = s[i][j] * scale;
                if (kmsk[c0s + j] == 0.f || kg > qg) v = NEGV;
                Ps[(r0 + i) * PPAD + c0s + j] = v;
            }
        }
        __syncthreads();

        // online softmax: 8 warps x 8 rows each, row width 32 = one warp
#pragma unroll
        for (int rr = 0; rr < 8; rr++) {
            int row = wid * 8 + rr;
            float v0 = Ps[row * PPAD + lane];
            float tm = v0;
#pragma unroll
            for (int off = 16; off > 0; off >>= 1)
                tm = fmaxf(tm, __shfl_xor_sync(0xFFFFFFFFu, tm, off));
            float mo = m_run[row];
            float mn = fmaxf(mo, tm);
            float p0 = __expf(v0 - mn);
            Ps[row * PPAD + lane] = p0;
            float ts = p0;
#pragma unroll
            for (int off = 16; off > 0; off >>= 1)
                ts += __shfl_xor_sync(0xFFFFFFFFu, ts, off);
            if (lane == 0) {
                float sc = __expf(mo - mn);
                scl[row]   = sc;
                l_run[row] = l_run[row] * sc + ts;
                m_run[row] = mn;
            }
        }
        __syncthreads();

        // rescale accumulators, then O += P V
#pragma unroll
        for (int i = 0; i < 4; i++) {
            float sc = scl[r0 + i];
#pragma unroll
            for (int j = 0; j < 4; j++) o[i][j] *= sc;
        }
#pragma unroll 8
        for (int k = 0; k < 32; k++) {
            float p[4];
#pragma unroll
            for (int i = 0; i < 4; i++) p[i] = Ps[(r0 + i) * PPAD + k];
            float4 vv = *(float4*)&Vs[k * TPAD + c0];
#pragma unroll
            for (int i = 0; i < 4; i++) {
                o[i][0] += p[i] * vv.x;
                o[i][1] += p[i] * vv.y;
                o[i][2] += p[i] * vv.z;
                o[i][3] += p[i] * vv.w;
            }
        }
    }

    // epilogue: normalize, query-mask, residual, store
#pragma unroll
    for (int i = 0; i < 4; i++) {
        int qg = qt * 64 + r0 + i;
        float fac = (1.0f / l_run[r0 + i]) * g_qmask[b * SEQ + qg];
        size_t base = (size_t)(b * SEQ + qg) * HID + h * DH + c0;
        float4 res;
        res.x = o[i][0] * fac + queries[base + 0];
        res.y = o[i][1] * fac + queries[base + 1];
        res.z = o[i][2] * fac + queries[base + 2];
        res.w = o[i][3] * fac + queries[base + 3];
        *(float4*)&out[base] = res;
    }
}

// ---------------- launcher --------------------------------------------------
extern "C" void kernel_launch(void* const* d_in, const int* in_sizes, int n_in,
                              void* d_out, int out_size) {
    const float* queries = (const float*)d_in[0];
    const float* keys    = (const float*)d_in[1];
    const float* Wq      = (const float*)d_in[2];
    const float* bq      = (const float*)d_in[3];
    const float* Wk      = (const float*)d_in[4];
    const float* bk      = (const float*)d_in[5];
    const float* Wv      = (const float*)d_in[6];
    const float* bv      = (const float*)d_in[7];
    float* out = (float*)d_out;

    // 1) masks: 2*32768 rows, 8 warps/block
    mask_kernel<<<(2 * ROWS) / 8, 256>>>(queries, keys);

    // 2) Q/K/V projections
    gemm_qkv<<<dim3(HID / 128, ROWS / 128, 3), 256>>>(queries, keys,
                                                      Wq, bq, Wk, bk, Wv, bv);

    // 3) flash attention + residual (static shared only; no attribute calls)
    attn_kernel<<<dim3(SEQ / 64, BATCH, NH), 256>>>(queries, out);
}

// round 4
// speedup vs baseline: 1.4091x; 1.4091x over previous
#include <cuda_runtime.h>
#include <math.h>
#include <stdint.h>

// Problem constants
#define BATCH 32
#define SEQ   1024
#define HID   512
#define NH    8
#define DH    64                 // head dim = 512/8
#define ROWS  (BATCH*SEQ)        // 32768
#define NEGV  (-4294967295.0f)   // -(2^32)+1, matches reference mask value

// ---------------- scratch (static device globals; no allocations) ----------
__device__ float g_q[(size_t)ROWS * HID];
__device__ float g_k[(size_t)ROWS * HID];
__device__ float g_v[(size_t)ROWS * HID];
__device__ float g_qmask[ROWS];
__device__ float g_kmask[ROWS];

// ---------------- kernel 1: masks -----------------------------------------
__global__ void mask_kernel(const float* __restrict__ queries,
                            const float* __restrict__ keys) {
    int row  = blockIdx.x * 8 + (threadIdx.x >> 5);   // 0 .. 2*ROWS-1
    int lane = threadIdx.x & 31;
    const float* src;
    float* dst;
    if (row < ROWS) { src = queries + (size_t)row * HID; dst = g_qmask + row; }
    else            { src = keys + (size_t)(row - ROWS) * HID; dst = g_kmask + (row - ROWS); }
    float s = 0.f;
#pragma unroll
    for (int i = 0; i < HID / 32; i++) s += src[lane + i * 32];
#pragma unroll
    for (int off = 16; off > 0; off >>= 1) s += __shfl_xor_sync(0xFFFFFFFFu, s, off);
    if (lane == 0) *dst = (s != 0.0f) ? 1.0f : 0.0f;
}

// ---------------- kernel 2: QKV projection GEMM (tf32 tensor cores) --------
// C[M=32768, N=512] = A @ W + bias, via mma.sync.m16n8k8.tf32.
// 128x128x32 CTA tile, 256 threads = 8 warps in 2(M) x 4(N); each warp 64x32.
#define APAD 36    // As row pitch (floats): 32 + 4
#define BPAD 132   // Bs row pitch (floats): 128 + 4

__device__ __forceinline__ uint32_t f2tf32(float x) {
    uint32_t r;
    asm("cvt.rna.tf32.f32 %0, %1;" : "=r"(r) : "f"(x));
    return r;
}

__global__ __launch_bounds__(256, 2)
void gemm_qkv(const float* __restrict__ queries, const float* __restrict__ keys,
              const float* __restrict__ Wq, const float* __restrict__ bq,
              const float* __restrict__ Wk, const float* __restrict__ bk,
              const float* __restrict__ Wv, const float* __restrict__ bv) {
    const float* A; const float* W; const float* bias; float* C;
    if (blockIdx.z == 0)      { A = queries; W = Wq; bias = bq; C = g_q; }
    else if (blockIdx.z == 1) { A = keys;    W = Wk; bias = bk; C = g_k; }
    else                      { A = keys;    W = Wv; bias = bv; C = g_v; }

    __shared__ uint32_t As[128 * APAD];   // [m][k], tf32 bits
    __shared__ uint32_t Bs[32 * BPAD];    // [k][n], tf32 bits

    const int tid    = threadIdx.x;
    const int wid    = tid >> 5;
    const int lane   = tid & 31;
    const int g      = lane >> 2;         // group id (0..7)
    const int t      = lane & 3;          // thread in group (0..3)
    const int warp_m = (wid & 1) * 64;
    const int warp_n = (wid >> 1) * 32;
    const int m0     = blockIdx.y * 128;
    const int n0     = blockIdx.x * 128;

    float acc[4][4][4];                   // [mt][nt][c0..c3]
#pragma unroll
    for (int mt = 0; mt < 4; mt++)
#pragma unroll
        for (int nt = 0; nt < 4; nt++)
#pragma unroll
            for (int c = 0; c < 4; c++) acc[mt][nt][c] = 0.f;

    for (int k0 = 0; k0 < HID; k0 += 32) {
        // A tile: 128 rows x 32 cols = 1024 float4
#pragma unroll
        for (int i = 0; i < 4; i++) {
            int idx = tid + i * 256;
            int row = idx >> 3;
            int col = (idx & 7) * 4;
            float4 v = *(const float4*)&A[(size_t)(m0 + row) * HID + k0 + col];
            uint32_t* d = &As[row * APAD + col];
            d[0] = f2tf32(v.x); d[1] = f2tf32(v.y);
            d[2] = f2tf32(v.z); d[3] = f2tf32(v.w);
        }
        // B tile: 32 rows x 128 cols = 1024 float4
#pragma unroll
        for (int i = 0; i < 4; i++) {
            int idx = tid + i * 256;
            int row = idx >> 5;
            int col = (idx & 31) * 4;
            float4 v = *(const float4*)&W[(size_t)(k0 + row) * HID + n0 + col];
            uint32_t* d = &Bs[row * BPAD + col];
            d[0] = f2tf32(v.x); d[1] = f2tf32(v.y);
            d[2] = f2tf32(v.z); d[3] = f2tf32(v.w);
        }
        __syncthreads();

#pragma unroll
        for (int ks = 0; ks < 32; ks += 8) {
            uint32_t af[4][4];   // [mt][a0..a3]
#pragma unroll
            for (int mt = 0; mt < 4; mt++) {
                int am = warp_m + mt * 16 + g;
                af[mt][0] = As[am * APAD + ks + t];
                af[mt][1] = As[(am + 8) * APAD + ks + t];
                af[mt][2] = As[am * APAD + ks + t + 4];
                af[mt][3] = As[(am + 8) * APAD + ks + t + 4];
            }
            uint32_t bf[4][2];   // [nt][b0..b1]
#pragma unroll
            for (int nt = 0; nt < 4; nt++) {
                int bn = warp_n + nt * 8 + g;
                bf[nt][0] = Bs[(ks + t) * BPAD + bn];
                bf[nt][1] = Bs[(ks + t + 4) * BPAD + bn];
            }
#pragma unroll
            for (int mt = 0; mt < 4; mt++)
#pragma unroll
                for (int nt = 0; nt < 4; nt++) {
                    asm volatile(
                        "mma.sync.aligned.m16n8k8.row.col.f32.tf32.tf32.f32 "
                        "{%0,%1,%2,%3}, {%4,%5,%6,%7}, {%8,%9}, {%0,%1,%2,%3};"
                        : "+f"(acc[mt][nt][0]), "+f"(acc[mt][nt][1]),
                          "+f"(acc[mt][nt][2]), "+f"(acc[mt][nt][3])
                        : "r"(af[mt][0]), "r"(af[mt][1]),
                          "r"(af[mt][2]), "r"(af[mt][3]),
                          "r"(bf[nt][0]), "r"(bf[nt][1]));
                }
        }
        __syncthreads();
    }

    // epilogue: bias + store
#pragma unroll
    for (int mt = 0; mt < 4; mt++) {
        int row0 = m0 + warp_m + mt * 16 + g;
#pragma unroll
        for (int nt = 0; nt < 4; nt++) {
            int col = n0 + warp_n + nt * 8 + t * 2;
            float b0 = bias[col], b1 = bias[col + 1];
            float2 lo = make_float2(acc[mt][nt][0] + b0, acc[mt][nt][1] + b1);
            float2 hi = make_float2(acc[mt][nt][2] + b0, acc[mt][nt][3] + b1);
            *(float2*)&C[(size_t)row0 * HID + col]       = lo;
            *(float2*)&C[(size_t)(row0 + 8) * HID + col] = hi;
        }
    }
}

// ---------------- kernel 3: flash attention (fp32) -------------------------
#define TPAD 68
#define PPAD 36

__global__ __launch_bounds__(256)
void attn_kernel(const float* __restrict__ queries, float* __restrict__ out) {
    const int qt = blockIdx.x;
    const int b  = blockIdx.y;
    const int h  = blockIdx.z;

    __shared__ float Qs[64 * TPAD];
    __shared__ float Ks[32 * TPAD];
    __shared__ float Vs[32 * TPAD];
    __shared__ float Ps[64 * PPAD];
    __shared__ float m_run[64], l_run[64], scl[64], kmsk[32];

    const int tid  = threadIdx.x;
    const int r0   = (tid >> 4) * 4;
    const int c0s  = (tid & 15) * 2;
    const int c0   = (tid & 15) * 4;
    const int wid  = tid >> 5;
    const int lane = tid & 31;

    const size_t headoff = (size_t)b * SEQ * HID + h * DH;
    const float* qbase = g_q + headoff;
    const float* kbase = g_k + headoff;
    const float* vbase = g_v + headoff;

#pragma unroll
    for (int i = 0; i < 4; i++) {
        int idx = tid + i * 256;
        int row = idx >> 4;
        int d4  = (idx & 15) * 4;
        *(float4*)&Qs[row * TPAD + d4] =
            *(const float4*)&qbase[(size_t)(qt * 64 + row) * HID + d4];
    }
    if (tid < 64) { m_run[tid] = -3.0e38f; l_run[tid] = 0.f; }

    float o[4][4];
#pragma unroll
    for (int i = 0; i < 4; i++)
#pragma unroll
        for (int j = 0; j < 4; j++) o[i][j] = 0.f;

    const float scale = 0.04419417382415922f;  // 1/sqrt(512)
    const int n_kt = 2 * qt + 2;

    for (int kt = 0; kt < n_kt; kt++) {
        __syncthreads();
#pragma unroll
        for (int i = 0; i < 2; i++) {
            int idx = tid + i * 256;
            int row = idx >> 4;
            int d4  = (idx & 15) * 4;
            size_t gidx = (size_t)(kt * 32 + row) * HID + d4;
            *(float4*)&Ks[row * TPAD + d4] = *(const float4*)&kbase[gidx];
            *(float4*)&Vs[row * TPAD + d4] = *(const float4*)&vbase[gidx];
        }
        if (tid < 32) kmsk[tid] = g_kmask[b * SEQ + kt * 32 + tid];
        __syncthreads();

        float s[4][2];
#pragma unroll
        for (int i = 0; i < 4; i++) { s[i][0] = 0.f; s[i][1] = 0.f; }
#pragma unroll
        for (int d0 = 0; d0 < DH; d0 += 4) {
            float4 qv[4], kv[2];
#pragma unroll
            for (int i = 0; i < 4; i++) qv[i] = *(float4*)&Qs[(r0 + i) * TPAD + d0];
#pragma unroll
            for (int j = 0; j < 2; j++) kv[j] = *(float4*)&Ks[(c0s + j) * TPAD + d0];
#pragma unroll
            for (int i = 0; i < 4; i++)
#pragma unroll
                for (int j = 0; j < 2; j++) {
                    s[i][j] += qv[i].x * kv[j].x + qv[i].y * kv[j].y
                             + qv[i].z * kv[j].z + qv[i].w * kv[j].w;
                }
        }
#pragma unroll
        for (int i = 0; i < 4; i++) {
            int qg = qt * 64 + r0 + i;
#pragma unroll
            for (int j = 0; j < 2; j++) {
                int kg = kt * 32 + c0s + j;
                float v = s[i][j] * scale;
                if (kmsk[c0s + j] == 0.f || kg > qg) v = NEGV;
                Ps[(r0 + i) * PPAD + c0s + j] = v;
            }
        }
        __syncthreads();

#pragma unroll
        for (int rr = 0; rr < 8; rr++) {
            int row = wid * 8 + rr;
            float v0 = Ps[row * PPAD + lane];
            float tm = v0;
#pragma unroll
            for (int off = 16; off > 0; off >>= 1)
                tm = fmaxf(tm, __shfl_xor_sync(0xFFFFFFFFu, tm, off));
            float mo = m_run[row];
            float mn = fmaxf(mo, tm);
            float p0 = __expf(v0 - mn);
            Ps[row * PPAD + lane] = p0;
            float ts = p0;
#pragma unroll
            for (int off = 16; off > 0; off >>= 1)
                ts += __shfl_xor_sync(0xFFFFFFFFu, ts, off);
            if (lane == 0) {
                float sc = __expf(mo - mn);
                scl[row]   = sc;
                l_run[row] = l_run[row] * sc + ts;
                m_run[row] = mn;
            }
        }
        __syncthreads();

#pragma unroll
        for (int i = 0; i < 4; i++) {
            float sc = scl[r0 + i];
#pragma unroll
            for (int j = 0; j < 4; j++) o[i][j] *= sc;
        }
#pragma unroll 8
        for (int k = 0; k < 32; k++) {
            float p[4];
#pragma unroll
            for (int i = 0; i < 4; i++) p[i] = Ps[(r0 + i) * PPAD + k];
            float4 vv = *(float4*)&Vs[k * TPAD + c0];
#pragma unroll
            for (int i = 0; i < 4; i++) {
                o[i][0] += p[i] * vv.x;
                o[i][1] += p[i] * vv.y;
                o[i][2] += p[i] * vv.z;
                o[i][3] += p[i] * vv.w;
            }
        }
    }

#pragma unroll
    for (int i = 0; i < 4; i++) {
        int qg = qt * 64 + r0 + i;
        float fac = (1.0f / l_run[r0 + i]) * g_qmask[b * SEQ + qg];
        size_t base = (size_t)(b * SEQ + qg) * HID + h * DH + c0;
        float4 res;
        res.x = o[i][0] * fac + queries[base + 0];
        res.y = o[i][1] * fac + queries[base + 1];
        res.z = o[i][2] * fac + queries[base + 2];
        res.w = o[i][3] * fac + queries[base + 3];
        *(float4*)&out[base] = res;
    }
}

// ---------------- launcher --------------------------------------------------
extern "C" void kernel_launch(void* const* d_in, const int* in_sizes, int n_in,
                              void* d_out, int out_size) {
    const float* queries = (const float*)d_in[0];
    const float* keys    = (const float*)d_in[1];
    const float* Wq      = (const float*)d_in[2];
    const float* bq      = (const float*)d_in[3];
    const float* Wk      = (const float*)d_in[4];
    const float* bk      = (const float*)d_in[5];
    const float* Wv      = (const float*)d_in[6];
    const float* bv      = (const float*)d_in[7];
    float* out = (float*)d_out;

    mask_kernel<<<(2 * ROWS) / 8, 256>>>(queries, keys);

    gemm_qkv<<<dim3(HID / 128, ROWS / 128, 3), 256>>>(queries, keys,
                                                      Wq, bq, Wk, bk, Wv, bv);

    attn_kernel<<<dim3(SEQ / 64, BATCH, NH), 256>>>(queries, out);
}

// round 5
// speedup vs baseline: 3.5763x; 2.5381x over previous
#include <cuda_runtime.h>
#include <math.h>
#include <stdint.h>

// Problem constants
#define BATCH 32
#define SEQ   1024
#define HID   512
#define NH    8
#define DH    64                 // head dim = 512/8
#define ROWS  (BATCH*SEQ)        // 32768
#define NEGV  (-4294967295.0f)   // -(2^32)+1, matches reference mask value

// ---------------- scratch (static device globals; no allocations) ----------
__device__ float g_q[(size_t)ROWS * HID];
__device__ float g_k[(size_t)ROWS * HID];
__device__ float g_v[(size_t)ROWS * HID];
__device__ float g_qmask[ROWS];
__device__ float g_kmask[ROWS];

__device__ __forceinline__ uint32_t f2tf32(float x) {
    uint32_t r;
    asm("cvt.rna.tf32.f32 %0, %1;" : "=r"(r) : "f"(x));
    return r;
}

// ---------------- kernel 1: masks -----------------------------------------
__global__ void mask_kernel(const float* __restrict__ queries,
                            const float* __restrict__ keys) {
    int row  = blockIdx.x * 8 + (threadIdx.x >> 5);   // 0 .. 2*ROWS-1
    int lane = threadIdx.x & 31;
    const float* src;
    float* dst;
    if (row < ROWS) { src = queries + (size_t)row * HID; dst = g_qmask + row; }
    else            { src = keys + (size_t)(row - ROWS) * HID; dst = g_kmask + (row - ROWS); }
    float s = 0.f;
#pragma unroll
    for (int i = 0; i < HID / 32; i++) s += src[lane + i * 32];
#pragma unroll
    for (int off = 16; off > 0; off >>= 1) s += __shfl_xor_sync(0xFFFFFFFFu, s, off);
    if (lane == 0) *dst = (s != 0.0f) ? 1.0f : 0.0f;
}

// ---------------- kernel 2: QKV projection GEMM (tf32 tensor cores) --------
#define APAD 36    // As row pitch: 32 + 4
#define BPAD 132   // Bs row pitch: 128 + 4

__global__ __launch_bounds__(256, 2)
void gemm_qkv(const float* __restrict__ queries, const float* __restrict__ keys,
              const float* __restrict__ Wq, const float* __restrict__ bq,
              const float* __restrict__ Wk, const float* __restrict__ bk,
              const float* __restrict__ Wv, const float* __restrict__ bv) {
    const float* A; const float* W; const float* bias; float* C;
    if (blockIdx.z == 0)      { A = queries; W = Wq; bias = bq; C = g_q; }
    else if (blockIdx.z == 1) { A = keys;    W = Wk; bias = bk; C = g_k; }
    else                      { A = keys;    W = Wv; bias = bv; C = g_v; }

    __shared__ uint32_t As[128 * APAD];
    __shared__ uint32_t Bs[32 * BPAD];

    const int tid    = threadIdx.x;
    const int wid    = tid >> 5;
    const int lane   = tid & 31;
    const int g      = lane >> 2;
    const int t      = lane & 3;
    const int warp_m = (wid & 1) * 64;
    const int warp_n = (wid >> 1) * 32;
    const int m0     = blockIdx.y * 128;
    const int n0     = blockIdx.x * 128;

    float acc[4][4][4];
#pragma unroll
    for (int mt = 0; mt < 4; mt++)
#pragma unroll
        for (int nt = 0; nt < 4; nt++)
#pragma unroll
            for (int c = 0; c < 4; c++) acc[mt][nt][c] = 0.f;

    for (int k0 = 0; k0 < HID; k0 += 32) {
#pragma unroll
        for (int i = 0; i < 4; i++) {
            int idx = tid + i * 256;
            int row = idx >> 3;
            int col = (idx & 7) * 4;
            float4 v = *(const float4*)&A[(size_t)(m0 + row) * HID + k0 + col];
            uint32_t* d = &As[row * APAD + col];
            d[0] = f2tf32(v.x); d[1] = f2tf32(v.y);
            d[2] = f2tf32(v.z); d[3] = f2tf32(v.w);
        }
#pragma unroll
        for (int i = 0; i < 4; i++) {
            int idx = tid + i * 256;
            int row = idx >> 5;
            int col = (idx & 31) * 4;
            float4 v = *(const float4*)&W[(size_t)(k0 + row) * HID + n0 + col];
            uint32_t* d = &Bs[row * BPAD + col];
            d[0] = f2tf32(v.x); d[1] = f2tf32(v.y);
            d[2] = f2tf32(v.z); d[3] = f2tf32(v.w);
        }
        __syncthreads();

#pragma unroll
        for (int ks = 0; ks < 32; ks += 8) {
            uint32_t af[4][4];
#pragma unroll
            for (int mt = 0; mt < 4; mt++) {
                int am = warp_m + mt * 16 + g;
                af[mt][0] = As[am * APAD + ks + t];
                af[mt][1] = As[(am + 8) * APAD + ks + t];
                af[mt][2] = As[am * APAD + ks + t + 4];
                af[mt][3] = As[(am + 8) * APAD + ks + t + 4];
            }
            uint32_t bf[4][2];
#pragma unroll
            for (int nt = 0; nt < 4; nt++) {
                int bn = warp_n + nt * 8 + g;
                bf[nt][0] = Bs[(ks + t) * BPAD + bn];
                bf[nt][1] = Bs[(ks + t + 4) * BPAD + bn];
            }
#pragma unroll
            for (int mt = 0; mt < 4; mt++)
#pragma unroll
                for (int nt = 0; nt < 4; nt++) {
                    asm volatile(
                        "mma.sync.aligned.m16n8k8.row.col.f32.tf32.tf32.f32 "
                        "{%0,%1,%2,%3}, {%4,%5,%6,%7}, {%8,%9}, {%0,%1,%2,%3};"
                        : "+f"(acc[mt][nt][0]), "+f"(acc[mt][nt][1]),
                          "+f"(acc[mt][nt][2]), "+f"(acc[mt][nt][3])
                        : "r"(af[mt][0]), "r"(af[mt][1]),
                          "r"(af[mt][2]), "r"(af[mt][3]),
                          "r"(bf[nt][0]), "r"(bf[nt][1]));
                }
        }
        __syncthreads();
    }

#pragma unroll
    for (int mt = 0; mt < 4; mt++) {
        int row0 = m0 + warp_m + mt * 16 + g;
#pragma unroll
        for (int nt = 0; nt < 4; nt++) {
            int col = n0 + warp_n + nt * 8 + t * 2;
            float b0 = bias[col], b1 = bias[col + 1];
            float2 lo = make_float2(acc[mt][nt][0] + b0, acc[mt][nt][1] + b1);
            float2 hi = make_float2(acc[mt][nt][2] + b0, acc[mt][nt][3] + b1);
            *(float2*)&C[(size_t)row0 * HID + col]       = lo;
            *(float2*)&C[(size_t)(row0 + 8) * HID + col] = hi;
        }
    }
}

// ---------------- kernel 3: flash attention (tf32 tensor cores) ------------
// grid (16 q-tiles, 32 batch, 8 heads), 128 threads = 4 warps.
// Warp w owns q-rows [qt*64 + w*16, +16) x all 64 keys of each K-tile.
// Q lives in registers as MMA A-fragments; K/V staged in smem as tf32.
// S and P live entirely in accumulator fragments (no smem P round trip).
#define KPITCH 68   // smem pitch for 64-wide K/V tiles

#define MMA_TF32(acc, a, b)                                            \
    asm volatile(                                                      \
        "mma.sync.aligned.m16n8k8.row.col.f32.tf32.tf32.f32 "          \
        "{%0,%1,%2,%3}, {%4,%5,%6,%7}, {%8,%9}, {%0,%1,%2,%3};"        \
        : "+f"((acc)[0]), "+f"((acc)[1]), "+f"((acc)[2]), "+f"((acc)[3]) \
        : "r"((a)[0]), "r"((a)[1]), "r"((a)[2]), "r"((a)[3]),          \
          "r"((b)[0]), "r"((b)[1]))

__global__ __launch_bounds__(128)
void attn_kernel(const float* __restrict__ queries, float* __restrict__ out) {
    const int qt = blockIdx.x;   // 0..15
    const int b  = blockIdx.y;   // 0..31
    const int h  = blockIdx.z;   // 0..7

    __shared__ uint32_t Ks[64 * KPITCH];   // tf32 bits, [key][d]
    __shared__ uint32_t Vs[64 * KPITCH];   // tf32 bits, [key][d]
    __shared__ float    kms[64];

    const int tid  = threadIdx.x;
    const int w    = tid >> 5;
    const int lane = tid & 31;
    const int g    = lane >> 2;          // fragment row within 8
    const int t    = lane & 3;           // fragment col group

    const size_t headoff = (size_t)b * SEQ * HID + h * DH;
    const float* qbase = g_q + headoff;
    const float* kbase = g_k + headoff;
    const float* vbase = g_v + headoff;

    const int row_l = qt * 64 + w * 16 + g;   // local row within batch (this thread's frag row)

    // Q fragments for all 8 k-steps (d = 64)
    uint32_t qf[8][4];
#pragma unroll
    for (int ks = 0; ks < 8; ks++) {
        int col = ks * 8 + t;
        qf[ks][0] = f2tf32(qbase[(size_t)row_l * HID + col]);
        qf[ks][1] = f2tf32(qbase[(size_t)(row_l + 8) * HID + col]);
        qf[ks][2] = f2tf32(qbase[(size_t)row_l * HID + col + 4]);
        qf[ks][3] = f2tf32(qbase[(size_t)(row_l + 8) * HID + col + 4]);
    }

    float o[8][4];
#pragma unroll
    for (int nt = 0; nt < 8; nt++)
#pragma unroll
        for (int c = 0; c < 4; c++) o[nt][c] = 0.f;

    float m0 = -3.0e38f, m1 = -3.0e38f, l0 = 0.f, l1 = 0.f;
    const float scale = 0.04419417382415922f;  // 1/sqrt(512)

    for (int kt = 0; kt <= qt; kt++) {
        __syncthreads();
        // load K, V tiles (64 keys x 64 d) as tf32
#pragma unroll
        for (int i = 0; i < 8; i++) {
            int idx = tid + i * 128;      // 0..1023 float4 slots
            int row = idx >> 4;
            int col = (idx & 15) * 4;
            size_t gidx = (size_t)(kt * 64 + row) * HID + col;
            float4 kv = *(const float4*)&kbase[gidx];
            float4 vv = *(const float4*)&vbase[gidx];
            uint32_t* kd = &Ks[row * KPITCH + col];
            kd[0] = f2tf32(kv.x); kd[1] = f2tf32(kv.y);
            kd[2] = f2tf32(kv.z); kd[3] = f2tf32(kv.w);
            uint32_t* vd = &Vs[row * KPITCH + col];
            vd[0] = f2tf32(vv.x); vd[1] = f2tf32(vv.y);
            vd[2] = f2tf32(vv.z); vd[3] = f2tf32(vv.w);
        }
        if (tid < 64) kms[tid] = g_kmask[b * SEQ + kt * 64 + tid];
        __syncthreads();

        // ---- S = Q K^T : 8 n-tiles (8 keys each) x 8 k-steps ----
        float s[8][4];
#pragma unroll
        for (int nt = 0; nt < 8; nt++) {
            s[nt][0] = 0.f; s[nt][1] = 0.f; s[nt][2] = 0.f; s[nt][3] = 0.f;
#pragma unroll
            for (int ks = 0; ks < 8; ks++) {
                uint32_t bf[2];
                bf[0] = Ks[(nt * 8 + g) * KPITCH + ks * 8 + t];
                bf[1] = Ks[(nt * 8 + g) * KPITCH + ks * 8 + t + 4];
                MMA_TF32(s[nt], qf[ks], bf);
            }
        }

        // ---- scale + masks (causal only on diagonal tile) ----
        const bool diag = (kt == qt);
#pragma unroll
        for (int nt = 0; nt < 8; nt++) {
            int c0 = nt * 8 + 2 * t;         // local col of s[nt][0]
            float km0 = kms[c0], km1 = kms[c0 + 1];
            int cg0 = kt * 64 + c0;
#pragma unroll
            for (int c = 0; c < 4; c++) {
                int colg = cg0 + (c & 1);
                int rowg = (c < 2) ? row_l : row_l + 8;
                float km = (c & 1) ? km1 : km0;
                float v = s[nt][c] * scale;
                if (km == 0.f || (diag && colg > rowg)) v = NEGV;
                s[nt][c] = v;
            }
        }

        // ---- online softmax on fragments ----
        float rm0 = -3.0e38f, rm1 = -3.0e38f;
#pragma unroll
        for (int nt = 0; nt < 8; nt++) {
            rm0 = fmaxf(rm0, fmaxf(s[nt][0], s[nt][1]));
            rm1 = fmaxf(rm1, fmaxf(s[nt][2], s[nt][3]));
        }
        rm0 = fmaxf(rm0, __shfl_xor_sync(0xFFFFFFFFu, rm0, 1));
        rm0 = fmaxf(rm0, __shfl_xor_sync(0xFFFFFFFFu, rm0, 2));
        rm1 = fmaxf(rm1, __shfl_xor_sync(0xFFFFFFFFu, rm1, 1));
        rm1 = fmaxf(rm1, __shfl_xor_sync(0xFFFFFFFFu, rm1, 2));

        float mn0 = fmaxf(m0, rm0);
        float mn1 = fmaxf(m1, rm1);
        float rs0 = 0.f, rs1 = 0.f;
#pragma unroll
        for (int nt = 0; nt < 8; nt++) {
            s[nt][0] = __expf(s[nt][0] - mn0);
            s[nt][1] = __expf(s[nt][1] - mn0);
            s[nt][2] = __expf(s[nt][2] - mn1);
            s[nt][3] = __expf(s[nt][3] - mn1);
            rs0 += s[nt][0] + s[nt][1];
            rs1 += s[nt][2] + s[nt][3];
        }
        rs0 += __shfl_xor_sync(0xFFFFFFFFu, rs0, 1);
        rs0 += __shfl_xor_sync(0xFFFFFFFFu, rs0, 2);
        rs1 += __shfl_xor_sync(0xFFFFFFFFu, rs1, 1);
        rs1 += __shfl_xor_sync(0xFFFFFFFFu, rs1, 2);

        float sc0 = __expf(m0 - mn0);
        float sc1 = __expf(m1 - mn1);
        l0 = l0 * sc0 + rs0;
        l1 = l1 * sc1 + rs1;
        m0 = mn0; m1 = mn1;
#pragma unroll
        for (int nt = 0; nt < 8; nt++) {
            o[nt][0] *= sc0; o[nt][1] *= sc0;
            o[nt][2] *= sc1; o[nt][3] *= sc1;
        }

        // ---- O += P V : permute P frags C-layout -> A-layout via quad shuffles
        const int src1 = (lane & ~3) | (t >> 1);
        const int src2 = src1 + 2;
#pragma unroll
        for (int kc = 0; kc < 8; kc++) {
            float x0 = __shfl_sync(0xFFFFFFFFu, s[kc][0], src1);
            float x1 = __shfl_sync(0xFFFFFFFFu, s[kc][1], src1);
            float y0 = __shfl_sync(0xFFFFFFFFu, s[kc][2], src1);
            float y1 = __shfl_sync(0xFFFFFFFFu, s[kc][3], src1);
            float z0 = __shfl_sync(0xFFFFFFFFu, s[kc][0], src2);
            float z1 = __shfl_sync(0xFFFFFFFFu, s[kc][1], src2);
            float u0 = __shfl_sync(0xFFFFFFFFu, s[kc][2], src2);
            float u1 = __shfl_sync(0xFFFFFFFFu, s[kc][3], src2);
            uint32_t pa[4];
            pa[0] = f2tf32((t & 1) ? x1 : x0);
            pa[1] = f2tf32((t & 1) ? y1 : y0);
            pa[2] = f2tf32((t & 1) ? z1 : z0);
            pa[3] = f2tf32((t & 1) ? u1 : u0);
#pragma unroll
            for (int nt2 = 0; nt2 < 8; nt2++) {
                uint32_t bf[2];
                bf[0] = Vs[(kc * 8 + t) * KPITCH + nt2 * 8 + g];
                bf[1] = Vs[(kc * 8 + t + 4) * KPITCH + nt2 * 8 + g];
                MMA_TF32(o[nt2], pa, bf);
            }
        }
    }

    // ---- epilogue: normalize, query-mask, residual, store ----
    const int grow0 = b * SEQ + row_l;          // global row (c0/c1)
    const float fac0 = (1.0f / l0) * g_qmask[grow0];
    const float fac1 = (1.0f / l1) * g_qmask[grow0 + 8];
#pragma unroll
    for (int nt2 = 0; nt2 < 8; nt2++) {
        int col = h * DH + nt2 * 8 + 2 * t;
        size_t a0 = (size_t)grow0 * HID + col;
        size_t a1 = (size_t)(grow0 + 8) * HID + col;
        float2 lo = make_float2(o[nt2][0] * fac0 + queries[a0],
                                o[nt2][1] * fac0 + queries[a0 + 1]);
        float2 hi = make_float2(o[nt2][2] * fac1 + queries[a1],
                                o[nt2][3] * fac1 + queries[a1 + 1]);
        *(float2*)&out[a0] = lo;
        *(float2*)&out[a1] = hi;
    }
}

// ---------------- launcher --------------------------------------------------
extern "C" void kernel_launch(void* const* d_in, const int* in_sizes, int n_in,
                              void* d_out, int out_size) {
    const float* queries = (const float*)d_in[0];
    const float* keys    = (const float*)d_in[1];
    const float* Wq      = (const float*)d_in[2];
    const float* bq      = (const float*)d_in[3];
    const float* Wk      = (const float*)d_in[4];
    const float* bk      = (const float*)d_in[5];
    const float* Wv      = (const float*)d_in[6];
    const float* bv      = (const float*)d_in[7];
    float* out = (float*)d_out;

    mask_kernel<<<(2 * ROWS) / 8, 256>>>(queries, keys);

    gemm_qkv<<<dim3(HID / 128, ROWS / 128, 3), 256>>>(queries, keys,
                                                      Wq, bq, Wk, bk, Wv, bv);

    attn_kernel<<<dim3(SEQ / 64, BATCH, NH), 128>>>(queries, out);
}

// round 7
// speedup vs baseline: 5.3406x; 1.4933x over previous
#include <cuda_runtime.h>
#include <cuda_bf16.h>
#include <math.h>
#include <stdint.h>

// Problem constants
#define BATCH 32
#define SEQ   1024
#define HID   512
#define NH    8
#define DH    64                 // head dim = 512/8
#define ROWS  (BATCH*SEQ)        // 32768
#define NEGV  (-4294967295.0f)   // -(2^32)+1, matches reference mask value

// ---------------- scratch (static device globals; no allocations) ----------
// q/k/v stored as bf16 bit patterns (uint16): MMA consumes bf16 anyway, so this
// rounding is free; halves scratch bandwidth.
__device__ uint16_t g_q[(size_t)ROWS * HID];
__device__ uint16_t g_k[(size_t)ROWS * HID];
__device__ uint16_t g_v[(size_t)ROWS * HID];
__device__ float    g_qmask[ROWS];
__device__ float    g_kmask[ROWS];

__device__ __forceinline__ uint32_t pack_bf16(float lo, float hi) {
    __nv_bfloat162 p = __floats2bfloat162_rn(lo, hi);   // x = lo (low half)
    return *reinterpret_cast<uint32_t*>(&p);
}

#define MMA_BF16(acc, a, b)                                              \
    asm volatile(                                                        \
        "mma.sync.aligned.m16n8k16.row.col.f32.bf16.bf16.f32 "           \
        "{%0,%1,%2,%3}, {%4,%5,%6,%7}, {%8,%9}, {%0,%1,%2,%3};"          \
        : "+f"((acc)[0]), "+f"((acc)[1]), "+f"((acc)[2]), "+f"((acc)[3]) \
        : "r"((a)[0]), "r"((a)[1]), "r"((a)[2]), "r"((a)[3]),            \
          "r"((b)[0]), "r"((b)[1]))

// ---------------- kernel 1: masks -----------------------------------------
__global__ void mask_kernel(const float* __restrict__ queries,
                            const float* __restrict__ keys) {
    int row  = blockIdx.x * 8 + (threadIdx.x >> 5);   // 0 .. 2*ROWS-1
    int lane = threadIdx.x & 31;
    const float* src;
    float* dst;
    if (row < ROWS) { src = queries + (size_t)row * HID; dst = g_qmask + row; }
    else            { src = keys + (size_t)(row - ROWS) * HID; dst = g_kmask + (row - ROWS); }
    float s = 0.f;
#pragma unroll
    for (int i = 0; i < HID / 32; i++) s += src[lane + i * 32];
#pragma unroll
    for (int off = 16; off > 0; off >>= 1) s += __shfl_xor_sync(0xFFFFFFFFu, s, off);
    if (lane == 0) *dst = (s != 0.0f) ? 1.0f : 0.0f;
}

// ---------------- kernel 2: QKV projection GEMM (bf16 tensor cores) --------
// C[M=32768, N=512] = bf16(A @ W + bias), via mma.sync.m16n8k16.bf16.
// 128x128x64 CTA tile, 256 threads = 8 warps in 2(M) x 4(N); warp tile 64x32.
#define GAP 72     // As pitch (bf16 units): 64 + 8 -> conflict-free A-frag loads
#define GBP 136    // Bs pitch (bf16 units): 128 + 8

__global__ __launch_bounds__(256, 2)
void gemm_qkv(const float* __restrict__ queries, const float* __restrict__ keys,
              const float* __restrict__ Wq, const float* __restrict__ bq,
              const float* __restrict__ Wk, const float* __restrict__ bk,
              const float* __restrict__ Wv, const float* __restrict__ bv) {
    const float* A; const float* W; const float* bias; uint16_t* C;
    if (blockIdx.z == 0)      { A = queries; W = Wq; bias = bq; C = g_q; }
    else if (blockIdx.z == 1) { A = keys;    W = Wk; bias = bk; C = g_k; }
    else                      { A = keys;    W = Wv; bias = bv; C = g_v; }

    __shared__ uint16_t As[128 * GAP];   // [m][k] bf16
    __shared__ uint16_t Bs[64 * GBP];    // [k][n] bf16

    const int tid    = threadIdx.x;
    const int wid    = tid >> 5;
    const int lane   = tid & 31;
    const int g      = lane >> 2;
    const int t      = lane & 3;
    const int warp_m = (wid & 1) * 64;
    const int warp_n = (wid >> 1) * 32;
    const int m0     = blockIdx.y * 128;
    const int n0     = blockIdx.x * 128;

    float acc[4][4][4];
#pragma unroll
    for (int mt = 0; mt < 4; mt++)
#pragma unroll
        for (int nt = 0; nt < 4; nt++)
#pragma unroll
            for (int c = 0; c < 4; c++) acc[mt][nt][c] = 0.f;

    for (int k0 = 0; k0 < HID; k0 += 64) {
        // A tile: 128 x 64 fp32 -> bf16 smem (2048 float4, 8 per thread)
#pragma unroll
        for (int i = 0; i < 8; i++) {
            int idx = tid + i * 256;
            int row = idx >> 4;
            int col = (idx & 15) * 4;
            float4 v = *(const float4*)&A[(size_t)(m0 + row) * HID + k0 + col];
            uint32_t* d = (uint32_t*)&As[row * GAP + col];
            d[0] = pack_bf16(v.x, v.y);
            d[1] = pack_bf16(v.z, v.w);
        }
        // B tile: 64 x 128 fp32 -> bf16 smem
#pragma unroll
        for (int i = 0; i < 8; i++) {
            int idx = tid + i * 256;
            int row = idx >> 5;
            int col = (idx & 31) * 4;
            float4 v = *(const float4*)&W[(size_t)(k0 + row) * HID + n0 + col];
            uint32_t* d = (uint32_t*)&Bs[row * GBP + col];
            d[0] = pack_bf16(v.x, v.y);
            d[1] = pack_bf16(v.z, v.w);
        }
        __syncthreads();

#pragma unroll
        for (int ks = 0; ks < 64; ks += 16) {
            uint32_t af[4][4];
#pragma unroll
            for (int mt = 0; mt < 4; mt++) {
                int am = warp_m + mt * 16 + g;
                af[mt][0] = *(uint32_t*)&As[am * GAP + ks + 2 * t];
                af[mt][1] = *(uint32_t*)&As[(am + 8) * GAP + ks + 2 * t];
                af[mt][2] = *(uint32_t*)&As[am * GAP + ks + 8 + 2 * t];
                af[mt][3] = *(uint32_t*)&As[(am + 8) * GAP + ks + 8 + 2 * t];
            }
            uint32_t bf[4][2];
#pragma unroll
            for (int nt = 0; nt < 4; nt++) {
                int bn = warp_n + nt * 8 + g;
                bf[nt][0] = (uint32_t)Bs[(ks + 2 * t) * GBP + bn]
                          | ((uint32_t)Bs[(ks + 2 * t + 1) * GBP + bn] << 16);
                bf[nt][1] = (uint32_t)Bs[(ks + 2 * t + 8) * GBP + bn]
                          | ((uint32_t)Bs[(ks + 2 * t + 9) * GBP + bn] << 16);
            }
#pragma unroll
            for (int mt = 0; mt < 4; mt++)
#pragma unroll
                for (int nt = 0; nt < 4; nt++)
                    MMA_BF16(acc[mt][nt], af[mt], bf[nt]);
        }
        __syncthreads();
    }

    // epilogue: bias + bf16 store
#pragma unroll
    for (int mt = 0; mt < 4; mt++) {
        int row0 = m0 + warp_m + mt * 16 + g;
#pragma unroll
        for (int nt = 0; nt < 4; nt++) {
            int col = n0 + warp_n + nt * 8 + t * 2;
            float b0 = bias[col], b1 = bias[col + 1];
            *(uint32_t*)&C[(size_t)row0 * HID + col] =
                pack_bf16(acc[mt][nt][0] + b0, acc[mt][nt][1] + b1);
            *(uint32_t*)&C[(size_t)(row0 + 8) * HID + col] =
                pack_bf16(acc[mt][nt][2] + b0, acc[mt][nt][3] + b1);
        }
    }
}

// ---------------- kernel 3: flash attention (bf16 tensor cores) ------------
// grid (16 q-tiles, 32 batch, 8 heads), 128 threads = 4 warps.
// Warp w owns q-rows [qt*64 + w*16, +16) x 64 keys per tile.
// S-frag (C layout) == PV A-frag layout for k16 -> no shuffles, just packs.
#define KP 72      // K/V smem pitch (bf16 units): 64 + 8

__global__ __launch_bounds__(128)
void attn_kernel(const float* __restrict__ queries, float* __restrict__ out) {
    const int qt = blockIdx.x;   // 0..15
    const int b  = blockIdx.y;   // 0..31
    const int h  = blockIdx.z;   // 0..7

    __shared__ uint16_t Ks[64 * KP];   // [key][d] bf16
    __shared__ uint16_t Vs[64 * KP];   // [key][d] bf16
    __shared__ float    kms[64];

    const int tid  = threadIdx.x;
    const int w    = tid >> 5;
    const int lane = tid & 31;
    const int g    = lane >> 2;
    const int t    = lane & 3;

    const size_t headoff = (size_t)b * SEQ * HID + h * DH;
    const uint16_t* qbase = g_q + headoff;
    const uint16_t* kbase = g_k + headoff;
    const uint16_t* vbase = g_v + headoff;

    const int row_l = qt * 64 + w * 16 + g;   // this thread's frag row (local)

    // Q fragments: 4 k-steps of 16 over d=64, packed bf16 pairs
    uint32_t qf[4][4];
#pragma unroll
    for (int ks = 0; ks < 4; ks++) {
        int col = ks * 16 + 2 * t;
        qf[ks][0] = *(const uint32_t*)&qbase[(size_t)row_l * HID + col];
        qf[ks][1] = *(const uint32_t*)&qbase[(size_t)(row_l + 8) * HID + col];
        qf[ks][2] = *(const uint32_t*)&qbase[(size_t)row_l * HID + col + 8];
        qf[ks][3] = *(const uint32_t*)&qbase[(size_t)(row_l + 8) * HID + col + 8];
    }

    float o[8][4];
#pragma unroll
    for (int nt = 0; nt < 8; nt++)
#pragma unroll
        for (int c = 0; c < 4; c++) o[nt][c] = 0.f;

    float m0 = -3.0e38f, m1 = -3.0e38f, l0 = 0.f, l1 = 0.f;
    const float scale = 0.04419417382415922f;  // 1/sqrt(512)

    for (int kt = 0; kt <= qt; kt++) {
        __syncthreads();
        // load K, V tiles (64 keys x 64 d, bf16): 512 uint4 each
#pragma unroll
        for (int i = 0; i < 4; i++) {
            int idx = tid + i * 128;
            int row = idx >> 3;
            int col = (idx & 7) * 8;
            size_t gidx = (size_t)(kt * 64 + row) * HID + col;
            uint4 kv = *(const uint4*)&kbase[gidx];
            uint4 vv = *(const uint4*)&vbase[gidx];
            uint32_t* kd = (uint32_t*)&Ks[row * KP + col];
            kd[0] = kv.x; kd[1] = kv.y; kd[2] = kv.z; kd[3] = kv.w;
            uint32_t* vd = (uint32_t*)&Vs[row * KP + col];
            vd[0] = vv.x; vd[1] = vv.y; vd[2] = vv.z; vd[3] = vv.w;
        }
        if (tid < 64) kms[tid] = g_kmask[b * SEQ + kt * 64 + tid];
        __syncthreads();

        // ---- S = Q K^T : 8 n-tiles x 4 k-steps ----
        float s[8][4];
#pragma unroll
        for (int nt = 0; nt < 8; nt++) {
            s[nt][0] = 0.f; s[nt][1] = 0.f; s[nt][2] = 0.f; s[nt][3] = 0.f;
            const uint16_t* krow = &Ks[(nt * 8 + g) * KP];
#pragma unroll
            for (int ks = 0; ks < 4; ks++) {
                uint32_t bf[2];
                bf[0] = *(const uint32_t*)&krow[ks * 16 + 2 * t];
                bf[1] = *(const uint32_t*)&krow[ks * 16 + 2 * t + 8];
                MMA_BF16(s[nt], qf[ks], bf);
            }
        }

        // ---- scale + masks (causal only on diagonal tile) ----
        const bool diag = (kt == qt);
#pragma unroll
        for (int nt = 0; nt < 8; nt++) {
            int c0 = nt * 8 + 2 * t;
            float km0 = kms[c0], km1 = kms[c0 + 1];
            int cg0 = kt * 64 + c0;
#pragma unroll
            for (int c = 0; c < 4; c++) {
                int colg = cg0 + (c & 1);
                int rowg = (c < 2) ? row_l : row_l + 8;
                float km = (c & 1) ? km1 : km0;
                float v = s[nt][c] * scale;
                if (km == 0.f || (diag && colg > rowg)) v = NEGV;
                s[nt][c] = v;
            }
        }

        // ---- online softmax on fragments ----
        float rm0 = -3.0e38f, rm1 = -3.0e38f;
#pragma unroll
        for (int nt = 0; nt < 8; nt++) {
            rm0 = fmaxf(rm0, fmaxf(s[nt][0], s[nt][1]));
            rm1 = fmaxf(rm1, fmaxf(s[nt][2], s[nt][3]));
        }
        rm0 = fmaxf(rm0, __shfl_xor_sync(0xFFFFFFFFu, rm0, 1));
        rm0 = fmaxf(rm0, __shfl_xor_sync(0xFFFFFFFFu, rm0, 2));
        rm1 = fmaxf(rm1, __shfl_xor_sync(0xFFFFFFFFu, rm1, 1));
        rm1 = fmaxf(rm1, __shfl_xor_sync(0xFFFFFFFFu, rm1, 2));

        float mn0 = fmaxf(m0, rm0);
        float mn1 = fmaxf(m1, rm1);
        float rs0 = 0.f, rs1 = 0.f;
#pragma unroll
        for (int nt = 0; nt < 8; nt++) {
            s[nt][0] = __expf(s[nt][0] - mn0);
            s[nt][1] = __expf(s[nt][1] - mn0);
            s[nt][2] = __expf(s[nt][2] - mn1);
            s[nt][3] = __expf(s[nt][3] - mn1);
            rs0 += s[nt][0] + s[nt][1];
            rs1 += s[nt][2] + s[nt][3];
        }
        rs0 += __shfl_xor_sync(0xFFFFFFFFu, rs0, 1);
        rs0 += __shfl_xor_sync(0xFFFFFFFFu, rs0, 2);
        rs1 += __shfl_xor_sync(0xFFFFFFFFu, rs1, 1);
        rs1 += __shfl_xor_sync(0xFFFFFFFFu, rs1, 2);

        float sc0 = __expf(m0 - mn0);
        float sc1 = __expf(m1 - mn1);
        l0 = l0 * sc0 + rs0;
        l1 = l1 * sc1 + rs1;
        m0 = mn0; m1 = mn1;
#pragma unroll
        for (int nt = 0; nt < 8; nt++) {
            o[nt][0] *= sc0; o[nt][1] *= sc0;
            o[nt][2] *= sc1; o[nt][3] *= sc1;
        }

        // ---- O += P V : C-frag layout == A-frag layout, just pack to bf16 --
#pragma unroll
        for (int kc = 0; kc < 4; kc++) {
            uint32_t pa[4];
            pa[0] = pack_bf16(s[2 * kc][0],     s[2 * kc][1]);
            pa[1] = pack_bf16(s[2 * kc][2],     s[2 * kc][3]);
            pa[2] = pack_bf16(s[2 * kc + 1][0], s[2 * kc + 1][1]);
            pa[3] = pack_bf16(s[2 * kc + 1][2], s[2 * kc + 1][3]);
            const uint16_t* v0 = &Vs[(kc * 16 + 2 * t) * KP];      // key 2t
            const uint16_t* v1 = &Vs[(kc * 16 + 2 * t + 1) * KP];  // key 2t+1
            const uint16_t* v2 = &Vs[(kc * 16 + 2 * t + 8) * KP];  // key 2t+8
            const uint16_t* v3 = &Vs[(kc * 16 + 2 * t + 9) * KP];  // key 2t+9
#pragma unroll
            for (int nt2 = 0; nt2 < 8; nt2++) {
                int d = nt2 * 8 + g;
                uint32_t bf[2];
                bf[0] = (uint32_t)v0[d] | ((uint32_t)v1[d] << 16);
                bf[1] = (uint32_t)v2[d] | ((uint32_t)v3[d] << 16);
                MMA_BF16(o[nt2], pa, bf);
            }
        }
    }

    // ---- epilogue: normalize, query-mask, residual, store ----
    const int grow0 = b * SEQ + row_l;
    const float fac0 = (1.0f / l0) * g_qmask[grow0];
    const float fac1 = (1.0f / l1) * g_qmask[grow0 + 8];
#pragma unroll
    for (int nt2 = 0; nt2 < 8; nt2++) {
        int col = h * DH + nt2 * 8 + 2 * t;
        size_t a0 = (size_t)grow0 * HID + col;
        size_t a1 = (size_t)(grow0 + 8) * HID + col;
        float2 lo = make_float2(o[nt2][0] * fac0 + queries[a0],
                                o[nt2][1] * fac0 + queries[a0 + 1]);
        float2 hi = make_float2(o[nt2][2] * fac1 + queries[a1],
                                o[nt2][3] * fac1 + queries[a1 + 1]);
        *(float2*)&out[a0] = lo;
        *(float2*)&out[a1] = hi;
    }
}

// ---------------- launcher --------------------------------------------------
extern "C" void kernel_launch(void* const* d_in, const int* in_sizes, int n_in,
                              void* d_out, int out_size) {
    const float* queries = (const float*)d_in[0];
    const float* keys    = (const float*)d_in[1];
    const float* Wq      = (const float*)d_in[2];
    const float* bq      = (const float*)d_in[3];
    const float* Wk      = (const float*)d_in[4];
    const float* bk      = (const float*)d_in[5];
    const float* Wv      = (const float*)d_in[6];
    const float* bv      = (const float*)d_in[7];
    float* out = (float*)d_out;

    mask_kernel<<<(2 * ROWS) / 8, 256>>>(queries, keys);

    gemm_qkv<<<dim3(HID / 128, ROWS / 128, 3), 256>>>(queries, keys,
                                                      Wq, bq, Wk, bk, Wv, bv);

    attn_kernel<<<dim3(SEQ / 64, BATCH, NH), 128>>>(queries, out);
}